// round 7
// baseline (speedup 1.0000x reference)
#include <cuda_runtime.h>
#include <cuda_bf16.h>
#include <math.h>
#include <stddef.h>

#define B_SZ    1024
#define T_ENC   128
#define N_INP   128
#define N_HID   256
#define T_DEC   24
#define DEC_STEPS 30

// ---------------- device scratch (no runtime alloc allowed) ----------------
__device__ float          g_xi   [(size_t)B_SZ * T_ENC * N_HID];   // 134 MB
__device__ float          g_mid  [(size_t)B_SZ * T_ENC * N_HID];   // 134 MB
__device__ __nv_bfloat16  g_uex  [(size_t)B_SZ * N_INP * N_HID];   //  67 MB
__device__ __nv_bfloat16  g_udmid[(size_t)B_SZ * T_ENC * N_HID];   //  67 MB
__device__ float g_h [B_SZ * N_HID];
__device__ float g_c [B_SZ * N_HID];
__device__ float g_hm[B_SZ * N_HID];
__device__ float g_cm[B_SZ * N_HID];
__device__ float g_hd[B_SZ * N_HID];
__device__ float g_cd[B_SZ * N_HID];
__device__ float g_q    [B_SZ * N_HID];
__device__ float g_xa   [B_SZ * N_INP];
__device__ float g_gates[B_SZ * 4 * N_HID];
__device__ float g_decin[B_SZ * N_HID];

// ---------------- helpers ----------------
__device__ __forceinline__ float tanhfast(float x) {
    float y; asm("tanh.approx.f32 %0, %1;" : "=f"(y) : "f"(x)); return y;
}
__device__ __forceinline__ float sigf(float x) {
    return 1.0f / (1.0f + expf(-x));
}

// ---------------- init: zero all recurrent state ----------------
__global__ void init_state_kernel() {
    int i = blockIdx.x * 256 + threadIdx.x;   // grid 1024 x 256 == B*N_HID
    g_h[i] = 0.f; g_c[i] = 0.f;
    g_hm[i] = 0.f; g_cm[i] = 0.f;
    g_hd[i] = 0.f; g_cd[i] = 0.f;
}

// ---------------- generic GEMM: Y = bias1+bias2+addin + A1*W1^T + A2*W2^T ----
// A: (M x K) row-major with stride lda.  W: (N x K) row-major with stride ldw.
// Requires M%64==0, N%64==0, K%16==0, lda%4==0, ldw%4==0 (all hold here).
__global__ void __launch_bounds__(256) gemm2_kernel(
    float* __restrict__ Yf, __nv_bfloat16* __restrict__ Yh,
    int M, int N,
    const float* __restrict__ A1, int lda1, const float* __restrict__ W1, int ldw1, int K1,
    const float* __restrict__ A2, int lda2, const float* __restrict__ W2, int ldw2, int K2,
    const float* __restrict__ bias1, const float* __restrict__ bias2,
    const float* __restrict__ addin, size_t ld_add)
{
    __shared__ float As[16][68];
    __shared__ float Ws[16][68];

    const int m0 = blockIdx.y * 64;
    const int n0 = blockIdx.x * 64;
    const int tid  = threadIdx.x;
    const int lrow = tid >> 2;           // 0..63
    const int lc4  = (tid & 3) * 4;      // 0,4,8,12
    const int tm0  = (tid >> 4) * 4;     // 0..60
    const int tn0  = (tid & 15) * 4;     // 0..60

    float acc[4][4] = {};

    #pragma unroll 1
    for (int seg = 0; seg < 2; seg++) {
        const float* A = seg ? A2 : A1;
        if (A == nullptr) continue;
        const float* W = seg ? W2 : W1;
        const int lda  = seg ? lda2 : lda1;
        const int ldw  = seg ? ldw2 : ldw1;
        const int K    = seg ? K2   : K1;

        const float* Arow = A + (size_t)(m0 + lrow) * lda + lc4;
        const float* Wrow = W + (size_t)(n0 + lrow) * ldw + lc4;

        #pragma unroll 1
        for (int k0 = 0; k0 < K; k0 += 16) {
            float4 av = *(const float4*)(Arow + k0);
            float4 wv = *(const float4*)(Wrow + k0);
            __syncthreads();
            As[lc4 + 0][lrow] = av.x; As[lc4 + 1][lrow] = av.y;
            As[lc4 + 2][lrow] = av.z; As[lc4 + 3][lrow] = av.w;
            Ws[lc4 + 0][lrow] = wv.x; Ws[lc4 + 1][lrow] = wv.y;
            Ws[lc4 + 2][lrow] = wv.z; Ws[lc4 + 3][lrow] = wv.w;
            __syncthreads();
            #pragma unroll
            for (int k = 0; k < 16; k++) {
                float4 a4 = *(const float4*)&As[k][tm0];
                float4 b4 = *(const float4*)&Ws[k][tn0];
                float am[4] = {a4.x, a4.y, a4.z, a4.w};
                float bn[4] = {b4.x, b4.y, b4.z, b4.w};
                #pragma unroll
                for (int i = 0; i < 4; i++)
                    #pragma unroll
                    for (int j = 0; j < 4; j++)
                        acc[i][j] += am[i] * bn[j];
            }
        }
    }

    float badd[4];
    #pragma unroll
    for (int j = 0; j < 4; j++) {
        float v = 0.f;
        if (bias1) v += bias1[n0 + tn0 + j];
        if (bias2) v += bias2[n0 + tn0 + j];
        badd[j] = v;
    }

    #pragma unroll
    for (int i = 0; i < 4; i++) {
        size_t m = (size_t)(m0 + tm0 + i);
        #pragma unroll
        for (int j = 0; j < 4; j++) {
            size_t n = (size_t)(n0 + tn0 + j);
            float v = acc[i][j] + badd[j];
            if (addin) v += addin[m * ld_add + n];
            if (Yf) Yf[m * (size_t)N + n] = v;
            else    Yh[m * (size_t)N + n] = __float2bfloat16(v);
        }
    }
}

// ---------------- P1: ue_x[b,j,k] = Ue_b[k] + sum_t inp[b,t,j]*UeW[k,t] ------
// grid (k-tiles=4, j-tiles=2, b=1024), 256 threads, 64x64 tile, K=128 (t dim)
__global__ void __launch_bounds__(256) uex_kernel(
    const float* __restrict__ inp, const float* __restrict__ UeW,
    const float* __restrict__ Ueb, __nv_bfloat16* __restrict__ uex)
{
    __shared__ float As[16][68];   // As[t][j]
    __shared__ float Ws[16][68];   // Ws[t][k]
    const int b  = blockIdx.z;
    const int j0 = blockIdx.y * 64;
    const int k0 = blockIdx.x * 64;
    const int tid  = threadIdx.x;
    const int lrow = tid >> 2;
    const int lc4  = (tid & 3) * 4;
    const int tm0  = (tid >> 4) * 4;    // j offset
    const int tn0  = (tid & 15) * 4;    // k offset
    const int jl   = tid & 63;
    const int tq   = tid >> 6;          // 0..3

    const float* ib = inp + (size_t)b * (T_ENC * N_INP);
    float acc[4][4] = {};

    #pragma unroll 1
    for (int t0 = 0; t0 < T_ENC; t0 += 16) {
        __syncthreads();
        #pragma unroll
        for (int p = 0; p < 4; p++) {
            int tt = tq + p * 4;
            As[tt][jl] = ib[(size_t)(t0 + tt) * N_INP + j0 + jl];
        }
        float4 wv = *(const float4*)(UeW + (size_t)(k0 + lrow) * T_ENC + t0 + lc4);
        Ws[lc4 + 0][lrow] = wv.x; Ws[lc4 + 1][lrow] = wv.y;
        Ws[lc4 + 2][lrow] = wv.z; Ws[lc4 + 3][lrow] = wv.w;
        __syncthreads();
        #pragma unroll
        for (int k = 0; k < 16; k++) {
            float4 a4 = *(const float4*)&As[k][tm0];
            float4 b4 = *(const float4*)&Ws[k][tn0];
            float am[4] = {a4.x, a4.y, a4.z, a4.w};
            float bn[4] = {b4.x, b4.y, b4.z, b4.w};
            #pragma unroll
            for (int i = 0; i < 4; i++)
                #pragma unroll
                for (int j = 0; j < 4; j++)
                    acc[i][j] += am[i] * bn[j];
        }
    }

    #pragma unroll
    for (int i = 0; i < 4; i++) {
        size_t row = (size_t)b * (N_INP * N_HID) + (size_t)(j0 + tm0 + i) * N_HID;
        #pragma unroll
        for (int j = 0; j < 4; j++) {
            float v = acc[i][j] + Ueb[k0 + tn0 + j];
            uex[row + k0 + tn0 + j] = __float2bfloat16(v);
        }
    }
}

// ---------------- encoder attention: score->softmax->xa ----------------
__global__ void __launch_bounds__(256) attn_enc_kernel(
    const float* __restrict__ q, const __nv_bfloat16* __restrict__ uex,
    const float* __restrict__ VeW, const float* __restrict__ VeB,
    const float* __restrict__ inp, int t, float* __restrict__ xa)
{
    const int b = blockIdx.x;
    const int tid = threadIdx.x;
    const int lane = tid & 31;
    const int w = tid >> 5;

    __shared__ float sq[256], sv[256], ssc[128], sred[256];
    sq[tid] = q[(size_t)b * N_HID + tid];
    sv[tid] = VeW[tid];
    __syncthreads();

    const __nv_bfloat16* ub = uex + (size_t)b * (N_INP * N_HID);
    const float veb = VeB[0];

    for (int j = w; j < N_INP; j += 8) {
        const __nv_bfloat162* up = (const __nv_bfloat162*)(ub + (size_t)j * N_HID);
        float s = 0.f;
        #pragma unroll
        for (int i = 0; i < 4; i++) {
            __nv_bfloat162 u2 = up[lane + 32 * i];
            int k = 64 * i + 2 * lane;
            s += sv[k]     * tanhfast(sq[k]     + __low2float(u2));
            s += sv[k + 1] * tanhfast(sq[k + 1] + __high2float(u2));
        }
        #pragma unroll
        for (int o = 16; o > 0; o >>= 1) s += __shfl_xor_sync(0xffffffffu, s, o);
        if (lane == 0) ssc[j] = s + veb;
    }
    __syncthreads();

    // softmax over 128
    float x = (tid < 128) ? ssc[tid] : -1e30f;
    sred[tid] = x; __syncthreads();
    #pragma unroll
    for (int o = 128; o > 0; o >>= 1) {
        if (tid < o) sred[tid] = fmaxf(sred[tid], sred[tid + o]);
        __syncthreads();
    }
    float mx = sred[0];
    __syncthreads();
    float e = (tid < 128) ? expf(x - mx) : 0.f;
    sred[tid] = e; __syncthreads();
    #pragma unroll
    for (int o = 128; o > 0; o >>= 1) {
        if (tid < o) sred[tid] += sred[tid + o];
        __syncthreads();
    }
    float inv = 1.0f / sred[0];
    if (tid < 128) {
        float xv = inp[((size_t)b * T_ENC + t) * N_INP + tid];
        xa[(size_t)b * N_INP + tid] = xv * e * inv;
    }
}

// ---------------- decoder attention: t scores + dec_in = sum_j t_j*mid[b,j,:] ---
__global__ void __launch_bounds__(256) attn_dec_kernel(
    const float* __restrict__ wd, const __nv_bfloat16* __restrict__ udmid,
    const float* __restrict__ VdW, const float* __restrict__ VdB,
    const float* __restrict__ mid, float* __restrict__ decin)
{
    const int b = blockIdx.x;
    const int tid = threadIdx.x;
    const int lane = tid & 31;
    const int w = tid >> 5;

    __shared__ float sq[256], sv[256], st[128];
    sq[tid] = wd[(size_t)b * N_HID + tid];
    sv[tid] = VdW[tid];
    __syncthreads();

    const __nv_bfloat16* ub = udmid + (size_t)b * (T_ENC * N_HID);
    const float vdb = VdB[0];

    for (int j = w; j < T_ENC; j += 8) {
        const __nv_bfloat162* up = (const __nv_bfloat162*)(ub + (size_t)j * N_HID);
        float s = 0.f;
        #pragma unroll
        for (int i = 0; i < 4; i++) {
            __nv_bfloat162 u2 = up[lane + 32 * i];
            int k = 64 * i + 2 * lane;
            s += sv[k]     * tanhfast(sq[k]     + __low2float(u2));
            s += sv[k + 1] * tanhfast(sq[k + 1] + __high2float(u2));
        }
        #pragma unroll
        for (int o = 16; o > 0; o >>= 1) s += __shfl_xor_sync(0xffffffffu, s, o);
        if (lane == 0) st[j] = s + vdb;
    }
    __syncthreads();

    // dec_in[h] = sum_j st[j] * mid[b, j, h]
    const float* mb = mid + (size_t)b * (T_ENC * N_HID) + tid;
    float acc = 0.f;
    #pragma unroll 8
    for (int j = 0; j < T_ENC; j++)
        acc += st[j] * mb[(size_t)j * N_HID];
    decin[(size_t)b * N_HID + tid] = acc;
}

// ---------------- LSTM cell (enc / mid): accurate activations ----------------
__global__ void __launch_bounds__(256) lstm_cell_kernel(
    const float* __restrict__ g, float* __restrict__ h, float* __restrict__ c,
    float* __restrict__ seq_out, int t)
{
    const int idx = blockIdx.x * 256 + threadIdx.x;    // B*N_HID
    const int b = idx >> 8;
    const int n = idx & 255;
    const float* gb = g + (size_t)b * (4 * N_HID);
    float gi = gb[n];
    float gf = gb[n + N_HID];
    float gg = gb[n + 2 * N_HID];
    float go = gb[n + 3 * N_HID];
    float c2 = sigf(gf) * c[idx] + sigf(gi) * tanhf(gg);
    float h2 = sigf(go) * tanhf(c2);
    c[idx] = c2;
    h[idx] = h2;
    if (seq_out) seq_out[((size_t)b * T_ENC + t) * N_HID + n] = h2;
}

// ---------------- decoder cell + regression output ----------------
__global__ void __launch_bounds__(256) dec_cell_out_kernel(
    const float* __restrict__ g, float* __restrict__ h, float* __restrict__ c,
    const float* __restrict__ regW, const float* __restrict__ regB,
    float* __restrict__ out, int step)
{
    const int b = blockIdx.x;
    const int n = threadIdx.x;
    const int idx = b * N_HID + n;
    const float* gb = g + (size_t)b * (4 * N_HID);
    float gi = gb[n];
    float gf = gb[n + N_HID];
    float gg = gb[n + 2 * N_HID];
    float go = gb[n + 3 * N_HID];
    float c2 = sigf(gf) * c[idx] + sigf(gi) * tanhf(gg);
    float h2 = sigf(go) * tanhf(c2);
    c[idx] = c2;
    h[idx] = h2;

    __shared__ float sr[256];
    sr[n] = regW[n] * h2;
    __syncthreads();
    #pragma unroll
    for (int o = 128; o > 0; o >>= 1) {
        if (n < o) sr[n] += sr[n + o];
        __syncthreads();
    }
    if (n == 0 && step >= DEC_STEPS - T_DEC)
        out[(size_t)b * T_DEC + (step - (DEC_STEPS - T_DEC))] = sr[0] + regB[0];
}

// ---------------- host launcher ----------------
extern "C" void kernel_launch(void* const* d_in, const int* in_sizes, int n_in,
                              void* d_out, int out_size)
{
    (void)in_sizes; (void)n_in; (void)out_size;
    const float* inp  = (const float*)d_in[0];
    const float* UeW  = (const float*)d_in[2];
    const float* Ueb  = (const float*)d_in[3];
    const float* Ue2W = (const float*)d_in[4];
    const float* Ue2b = (const float*)d_in[5];
    const float* WeW  = (const float*)d_in[6];
    const float* Web  = (const float*)d_in[7];
    const float* VeW  = (const float*)d_in[8];
    const float* Veb  = (const float*)d_in[9];
    const float* UdW  = (const float*)d_in[10];
    const float* Udb  = (const float*)d_in[11];
    const float* WdW  = (const float*)d_in[12];
    const float* Wdb  = (const float*)d_in[13];
    const float* VdW  = (const float*)d_in[14];
    const float* Vdb  = (const float*)d_in[15];
    const float* eWih = (const float*)d_in[16];
    const float* eWhh = (const float*)d_in[17];
    const float* ebih = (const float*)d_in[18];
    const float* ebhh = (const float*)d_in[19];
    const float* mWih = (const float*)d_in[20];
    const float* mWhh = (const float*)d_in[21];
    const float* mbih = (const float*)d_in[22];
    const float* mbhh = (const float*)d_in[23];
    const float* dWih = (const float*)d_in[24];
    const float* dWhh = (const float*)d_in[25];
    const float* dbih = (const float*)d_in[26];
    const float* dbhh = (const float*)d_in[27];
    const float* regW = (const float*)d_in[28];
    const float* regb = (const float*)d_in[29];
    float* out = (float*)d_out;

    float *xi, *mid, *h, *c, *hm, *cm, *hd, *cd, *q, *xa, *g, *decin;
    __nv_bfloat16 *uex, *udmid;
    cudaGetSymbolAddress((void**)&xi,    g_xi);
    cudaGetSymbolAddress((void**)&mid,   g_mid);
    cudaGetSymbolAddress((void**)&uex,   g_uex);
    cudaGetSymbolAddress((void**)&udmid, g_udmid);
    cudaGetSymbolAddress((void**)&h,     g_h);
    cudaGetSymbolAddress((void**)&c,     g_c);
    cudaGetSymbolAddress((void**)&hm,    g_hm);
    cudaGetSymbolAddress((void**)&cm,    g_cm);
    cudaGetSymbolAddress((void**)&hd,    g_hd);
    cudaGetSymbolAddress((void**)&cd,    g_cd);
    cudaGetSymbolAddress((void**)&q,     g_q);
    cudaGetSymbolAddress((void**)&xa,    g_xa);
    cudaGetSymbolAddress((void**)&g,     g_gates);
    cudaGetSymbolAddress((void**)&decin, g_decin);

    init_state_kernel<<<1024, 256>>>();

    // P1: ue_x (bf16)
    uex_kernel<<<dim3(4, 2, 1024), 256>>>(inp, UeW, Ueb, uex);

    // P2: xi_all = inputs @ Ue2W^T + b  (M = B*T = 131072)
    gemm2_kernel<<<dim3(4, 2048), 256>>>(
        xi, nullptr, B_SZ * T_ENC, N_HID,
        inp, N_INP, Ue2W, N_INP, N_INP,
        nullptr, 0, nullptr, 0, 0,
        Ue2b, nullptr, nullptr, 0);

    // -------- encoder + mid recurrence --------
    for (int t = 0; t < T_ENC; t++) {
        // q = We_b + [h|c] @ WeW^T + xi[:, t, :]
        gemm2_kernel<<<dim3(4, 16), 256>>>(
            q, nullptr, B_SZ, N_HID,
            h, N_HID, WeW, 2 * N_HID, N_HID,
            c, N_HID, WeW + N_HID, 2 * N_HID, N_HID,
            Web, nullptr, xi + (size_t)t * N_HID, (size_t)T_ENC * N_HID);

        attn_enc_kernel<<<B_SZ, 256>>>(q, uex, VeW, Veb, inp, t, xa);

        // enc gates = bih + bhh + xa @ Wih^T + h @ Whh^T
        gemm2_kernel<<<dim3(16, 16), 256>>>(
            g, nullptr, B_SZ, 4 * N_HID,
            xa, N_INP, eWih, N_INP, N_INP,
            h, N_HID, eWhh, N_HID, N_HID,
            ebih, ebhh, nullptr, 0);

        lstm_cell_kernel<<<1024, 256>>>(g, h, c, nullptr, 0);

        // mid gates = bih + bhh + h_enc @ Wih^T + hm @ Whh^T
        gemm2_kernel<<<dim3(16, 16), 256>>>(
            g, nullptr, B_SZ, 4 * N_HID,
            h, N_HID, mWih, N_HID, N_HID,
            hm, N_HID, mWhh, N_HID, N_HID,
            mbih, mbhh, nullptr, 0);

        lstm_cell_kernel<<<1024, 256>>>(g, hm, cm, mid, t);
    }

    // P3: ud_mid = mid @ UdW^T + b  (bf16 out)
    gemm2_kernel<<<dim3(4, 2048), 256>>>(
        nullptr, udmid, B_SZ * T_ENC, N_HID,
        mid, N_HID, UdW, N_HID, N_HID,
        nullptr, 0, nullptr, 0, 0,
        Udb, nullptr, nullptr, 0);

    // -------- decoder --------
    for (int s = 0; s < DEC_STEPS; s++) {
        // wd = Wd_b + [hd|cd] @ WdW^T  (reuse q buffer)
        gemm2_kernel<<<dim3(4, 16), 256>>>(
            q, nullptr, B_SZ, N_HID,
            hd, N_HID, WdW, 2 * N_HID, N_HID,
            cd, N_HID, WdW + N_HID, 2 * N_HID, N_HID,
            Wdb, nullptr, nullptr, 0);

        attn_dec_kernel<<<B_SZ, 256>>>(q, udmid, VdW, Vdb, mid, decin);

        gemm2_kernel<<<dim3(16, 16), 256>>>(
            g, nullptr, B_SZ, 4 * N_HID,
            decin, N_HID, dWih, N_HID, N_HID,
            hd, N_HID, dWhh, N_HID, N_HID,
            dbih, dbhh, nullptr, 0);

        dec_cell_out_kernel<<<B_SZ, 256>>>(g, hd, cd, regW, regb, out, s);
    }
}